// round 6
// baseline (speedup 1.0000x reference)
#include <cuda_runtime.h>
#include <cuda_bf16.h>

#define IN_F  8192
#define OUT_F 8192
#define THRESH 50.0f
#define NTHREADS 256
#define WARPS_PER_CTA (NTHREADS / 32)
#define V4_PER_LANE (IN_F / 4 / 32)      // 64 float4 per lane per row
#define UNROLL 8

__global__ __launch_bounds__(NTHREADS, 4)
void snn_warprow_kernel(const float* __restrict__ x,
                        const float* __restrict__ syn,
                        const float* __restrict__ mem,
                        const float* __restrict__ thr,
                        const float* __restrict__ trace,
                        const float* __restrict__ refr,
                        float* __restrict__ out_spk,
                        float* __restrict__ out_mem,
                        float* __restrict__ out_trace,
                        float* __restrict__ out_refr)
{
    const int warp = threadIdx.x >> 5;
    const int lane = threadIdx.x & 31;
    const int row  = blockIdx.x * WARPS_PER_CTA + warp;

    const float4* __restrict__ x4 = reinterpret_cast<const float4*>(x);
    const float4* __restrict__ syn4 =
        reinterpret_cast<const float4*>(syn + (size_t)row * IN_F);

    // ---- pass 1: masked GEMV over this warp's row (no inter-warp sync) ----
    float acc = 0.0f;
    #pragma unroll 2
    for (int c = 0; c < V4_PER_LANE; c += UNROLL) {
        float4 s[UNROLL];
        #pragma unroll
        for (int j = 0; j < UNROLL; ++j)
            s[j] = __ldcs(&syn4[lane + (c + j) * 32]);     // batched, streaming
        #pragma unroll
        for (int j = 0; j < UNROLL; ++j) {
            const float4 xv = __ldca(&x4[lane + (c + j) * 32]);  // L1-resident
            acc += (s[j].x > THRESH) ? xv.x : 0.0f;
            acc += (s[j].y > THRESH) ? xv.y : 0.0f;
            acc += (s[j].z > THRESH) ? xv.z : 0.0f;
            acc += (s[j].w > THRESH) ? xv.w : 0.0f;
        }
    }

    // butterfly reduce: every lane ends with the full row sum
    #pragma unroll
    for (int o = 16; o > 0; o >>= 1)
        acc += __shfl_xor_sync(0xffffffffu, acc, o);

    // ---- LIF scalars (uniform across the warp) ----
    const float r     = __ldg(&refr[row]);
    const float v_mem = __ldg(&mem[row]) * 0.5f + acc * (1.0f - r * 0.5f);
    const float sp    = (v_mem >= __ldg(&thr[row])) ? 1.0f : 0.0f;
    if (lane == 0) {
        out_spk[row]  = sp;
        out_mem[row]  = v_mem * (1.0f - sp);
        out_refr[row] = fminf(fmaxf(r + sp - 0.1f, 0.0f), 1.0f);
    }

    // ---- pass 2: eligibility trace stream for this row ----
    const float4* __restrict__ tr4 =
        reinterpret_cast<const float4*>(trace + (size_t)row * IN_F);
    float4* __restrict__ ot4 =
        reinterpret_cast<float4*>(out_trace + (size_t)row * IN_F);

    #pragma unroll 2
    for (int c = 0; c < V4_PER_LANE; c += UNROLL) {
        float4 t[UNROLL];
        #pragma unroll
        for (int j = 0; j < UNROLL; ++j)
            t[j] = __ldcs(&tr4[lane + (c + j) * 32]);      // batched, streaming
        #pragma unroll
        for (int j = 0; j < UNROLL; ++j) {
            const int idx = lane + (c + j) * 32;
            const float4 xv = __ldca(&x4[idx]);
            float4 o;
            o.x = fminf(fmaxf(fmaf(t[j].x, 0.8f, sp * xv.x), 0.0f), 5.0f);
            o.y = fminf(fmaxf(fmaf(t[j].y, 0.8f, sp * xv.y), 0.0f), 5.0f);
            o.z = fminf(fmaxf(fmaf(t[j].z, 0.8f, sp * xv.z), 0.0f), 5.0f);
            o.w = fminf(fmaxf(fmaf(t[j].w, 0.8f, sp * xv.w), 0.0f), 5.0f);
            __stcs(&ot4[idx], o);
        }
    }
}

extern "C" void kernel_launch(void* const* d_in, const int* in_sizes, int n_in,
                              void* d_out, int out_size) {
    const float* x     = (const float*)d_in[0];  // spike_input        [8192]
    const float* syn   = (const float*)d_in[1];  // synapse_states     [8192*8192]
    const float* mem   = (const float*)d_in[2];  // membrane_potential [8192]
    const float* thr   = (const float*)d_in[3];  // adaptive_threshold [8192]
    const float* trace = (const float*)d_in[4];  // eligibility_trace  [8192*8192]
    const float* refr  = (const float*)d_in[5];  // refractory_period  [8192]

    float* out = (float*)d_out;
    // output layout: spikes | new_membrane | new_trace | new_refractory
    float* out_spk   = out;
    float* out_mem   = out + OUT_F;
    float* out_trace = out + 2 * OUT_F;
    float* out_refr  = out + 2 * OUT_F + (size_t)OUT_F * IN_F;

    snn_warprow_kernel<<<OUT_F / WARPS_PER_CTA, NTHREADS>>>(
        x, syn, mem, thr, trace, refr,
        out_spk, out_mem, out_trace, out_refr);
}